// round 1
// baseline (speedup 1.0000x reference)
#include <cuda_runtime.h>
#include <math.h>

// Problem constants (fixed by the dataset)
#define L_DIM 16384
#define H_DIM 1024

// Tiling: each block handles CHUNK rows x 512 channels.
// 128 threads/block, each thread owns 4 adjacent channels (float4).
#define CHUNK  128
#define GROUPS 2          // H / 512
#define TPB    128

__device__ __forceinline__ float4 ld4(const float* p) {
    return *reinterpret_cast<const float4*>(p);
}
__device__ __forceinline__ void st4(float* p, float4 v) {
    *reinterpret_cast<float4*>(p) = v;
}

__global__ __launch_bounds__(TPB)
void LI_scan_kernel(const float* __restrict__ x,
                    const float* __restrict__ tau,
                    float* __restrict__ out) {
    const int chunk       = blockIdx.x;
    const int chunk_start = chunk * CHUNK;
    const int ch          = (blockIdx.y * TPB + threadIdx.x) * 4;

    // Per-channel decay A = exp(tau)
    float4 t = ld4(tau + ch);
    float4 A;
    A.x = expf(t.x); A.y = expf(t.y); A.z = expf(t.z); A.w = expf(t.w);

    // Runtime halo length K: smallest K with Amax^K < 1e-10 (then the
    // truncated prefix differs from the exact scan by < ~1e-9 relative).
    // Falls back to the exact full prefix (K = chunk_start) if A is ~1 or >1.
    float amax = fmaxf(fmaxf(A.x, A.y), fmaxf(A.z, A.w));
    int K;
    if (!(amax < 0.999999f)) {
        K = chunk_start;                       // no usable decay: exact prefix
    } else if (amax <= 1e-12f) {
        K = 0;                                 // instant decay
    } else {
        float kf = logf(1e-10f) / logf(amax);  // both logs negative -> positive
        int   ki = (int)ceilf(kf);
        K = ki < chunk_start ? ki : chunk_start;
        if (K < 0) K = 0;
    }

    // Block-uniform K (keeps the batched loops aligned across the block)
    __shared__ int sK;
    if (threadIdx.x == 0) sK = 0;
    __syncthreads();
    atomicMax(&sK, K);
    __syncthreads();
    K = sK;

    const float* px = x + ch;
    float*       po = out + ch;

    float4 acc = make_float4(0.f, 0.f, 0.f, 0.f);

    // ---- Halo warm-up: rows [chunk_start-K, chunk_start), no stores ----
    int row = chunk_start - K;
    int rem = K & 7;
    for (int r = 0; r < rem; ++r, ++row) {
        float4 v = ld4(px + (size_t)row * H_DIM);
        acc.x = fmaf(A.x, acc.x, v.x);
        acc.y = fmaf(A.y, acc.y, v.y);
        acc.z = fmaf(A.z, acc.z, v.z);
        acc.w = fmaf(A.w, acc.w, v.w);
    }
    for (; row < chunk_start; row += 8) {
        float4 v[8];
        #pragma unroll
        for (int j = 0; j < 8; ++j)
            v[j] = ld4(px + (size_t)(row + j) * H_DIM);   // 8 outstanding LDG.128
        #pragma unroll
        for (int j = 0; j < 8; ++j) {
            acc.x = fmaf(A.x, acc.x, v[j].x);
            acc.y = fmaf(A.y, acc.y, v[j].y);
            acc.z = fmaf(A.z, acc.z, v[j].z);
            acc.w = fmaf(A.w, acc.w, v[j].w);
        }
    }

    // ---- Main chunk: rows [chunk_start, chunk_start+CHUNK), with stores ----
    const int chunk_end = chunk_start + CHUNK;
    for (int l = chunk_start; l < chunk_end; l += 8) {
        float4 v[8];
        #pragma unroll
        for (int j = 0; j < 8; ++j)
            v[j] = ld4(px + (size_t)(l + j) * H_DIM);
        #pragma unroll
        for (int j = 0; j < 8; ++j) {
            acc.x = fmaf(A.x, acc.x, v[j].x);
            acc.y = fmaf(A.y, acc.y, v[j].y);
            acc.z = fmaf(A.z, acc.z, v[j].z);
            acc.w = fmaf(A.w, acc.w, v[j].w);
            st4(po + (size_t)(l + j) * H_DIM, acc);
        }
    }
}

extern "C" void kernel_launch(void* const* d_in, const int* in_sizes, int n_in,
                              void* d_out, int out_size) {
    const float* x   = (const float*)d_in[0];   // (L, H) fp32
    const float* tau = (const float*)d_in[1];   // (H,)   fp32
    float*       out = (float*)d_out;           // (L, H) fp32

    dim3 grid(L_DIM / CHUNK, GROUPS);
    LI_scan_kernel<<<grid, TPB>>>(x, tau, out);
}

// round 2
// speedup vs baseline: 1.4615x; 1.4615x over previous
#include <cuda_runtime.h>
#include <math.h>

// Problem constants (fixed by the dataset)
#define L_DIM 16384
#define H_DIM 1024

// Tiling: each block handles CHUNK rows x 512 channels.
// 128 threads/block, each thread owns 4 adjacent channels (float4).
#define CHUNK  64
#define GROUPS 2          // H / 512
#define TPB    128
#define BATCH  8          // outstanding LDG.128 per thread

__device__ __forceinline__ float4 ld4(const float* p) {
    return *reinterpret_cast<const float4*>(p);
}
__device__ __forceinline__ void st4(float* p, float4 v) {
    *reinterpret_cast<float4*>(p) = v;
}

// min 3 blocks/SM -> reg budget ~168/thread: lets ptxas keep all BATCH float4
// load buffers live (the round-1 kernel was clamped to 32 regs and lost MLP).
__global__ __launch_bounds__(TPB, 3)
void LI_scan_kernel(const float* __restrict__ x,
                    const float* __restrict__ tau,
                    float* __restrict__ out) {
    const int chunk       = blockIdx.x;
    const int chunk_start = chunk * CHUNK;
    const int ch          = (blockIdx.y * TPB + threadIdx.x) * 4;

    // Per-channel decay A = exp(tau)
    float4 t = ld4(tau + ch);
    float4 A;
    A.x = expf(t.x); A.y = expf(t.y); A.z = expf(t.z); A.w = expf(t.w);

    // Runtime halo length K: smallest K with Amax^K < 1e-10 (then the
    // truncated prefix differs from the exact scan by < ~1e-9 relative).
    // Falls back to the exact full prefix (K = chunk_start) if A is ~1 or >1.
    float amax = fmaxf(fmaxf(A.x, A.y), fmaxf(A.z, A.w));
    int K;
    if (!(amax < 0.999999f)) {
        K = chunk_start;                       // no usable decay: exact prefix
    } else if (amax <= 1e-12f) {
        K = 0;                                 // instant decay
    } else {
        float kf = logf(1e-10f) / logf(amax);  // both logs negative -> positive
        int   ki = (int)ceilf(kf);
        K = ki < chunk_start ? ki : chunk_start;
        if (K < 0) K = 0;
    }

    // Block-uniform K (keeps the batched loops aligned across the block)
    __shared__ int sK;
    if (threadIdx.x == 0) sK = 0;
    __syncthreads();
    atomicMax(&sK, K);
    __syncthreads();
    K = sK;

    const float* px = x + ch;
    float*       po = out + ch;

    float4 acc = make_float4(0.f, 0.f, 0.f, 0.f);

    // ---- Halo warm-up: rows [chunk_start-K, chunk_start), no stores ----
    int row = chunk_start - K;
    int rem = K & (BATCH - 1);
    for (int r = 0; r < rem; ++r, ++row) {
        float4 v = ld4(px + (size_t)row * H_DIM);
        acc.x = fmaf(A.x, acc.x, v.x);
        acc.y = fmaf(A.y, acc.y, v.y);
        acc.z = fmaf(A.z, acc.z, v.z);
        acc.w = fmaf(A.w, acc.w, v.w);
    }
    for (; row < chunk_start; row += BATCH) {
        float4 v[BATCH];
        #pragma unroll
        for (int j = 0; j < BATCH; ++j)
            v[j] = ld4(px + (size_t)(row + j) * H_DIM);   // BATCH outstanding LDG.128
        #pragma unroll
        for (int j = 0; j < BATCH; ++j) {
            acc.x = fmaf(A.x, acc.x, v[j].x);
            acc.y = fmaf(A.y, acc.y, v[j].y);
            acc.z = fmaf(A.z, acc.z, v[j].z);
            acc.w = fmaf(A.w, acc.w, v[j].w);
        }
    }

    // ---- Main chunk: rows [chunk_start, chunk_start+CHUNK), with stores ----
    const int chunk_end = chunk_start + CHUNK;
    for (int l = chunk_start; l < chunk_end; l += BATCH) {
        float4 v[BATCH];
        #pragma unroll
        for (int j = 0; j < BATCH; ++j)
            v[j] = ld4(px + (size_t)(l + j) * H_DIM);
        #pragma unroll
        for (int j = 0; j < BATCH; ++j) {
            acc.x = fmaf(A.x, acc.x, v[j].x);
            acc.y = fmaf(A.y, acc.y, v[j].y);
            acc.z = fmaf(A.z, acc.z, v[j].z);
            acc.w = fmaf(A.w, acc.w, v[j].w);
            st4(po + (size_t)(l + j) * H_DIM, acc);
        }
    }
}

extern "C" void kernel_launch(void* const* d_in, const int* in_sizes, int n_in,
                              void* d_out, int out_size) {
    const float* x   = (const float*)d_in[0];   // (L, H) fp32
    const float* tau = (const float*)d_in[1];   // (H,)   fp32
    float*       out = (float*)d_out;           // (L, H) fp32

    dim3 grid(L_DIM / CHUNK, GROUPS);
    LI_scan_kernel<<<grid, TPB>>>(x, tau, out);
}

// round 3
// speedup vs baseline: 2.2908x; 1.5674x over previous
#include <cuda_runtime.h>
#include <math.h>

// Problem constants (fixed by the dataset)
#define L_DIM 16384
#define H_DIM 1024

// Tiling: each block handles CHUNK rows x 512 channels.
// 128 threads/block, each thread owns 4 adjacent channels (float4).
#define CHUNK  64
#define GROUPS 2          // H / 512
#define TPB    128
#define BATCH  8          // outstanding LDG.128 per thread per buffer

__device__ __forceinline__ float4 ld4(const float* p) {
    return *reinterpret_cast<const float4*>(p);
}

__device__ __forceinline__ void loadB(float4 v[BATCH], const float* px, int row) {
#pragma unroll
    for (int j = 0; j < BATCH; ++j)
        v[j] = ld4(px + (size_t)(row + j) * H_DIM);   // BATCH back-to-back LDG.128
}

__device__ __forceinline__ void procB(const float4 v[BATCH], float4 A, float4& acc,
                                      float* po, int row, bool store) {
#pragma unroll
    for (int j = 0; j < BATCH; ++j) {
        acc.x = fmaf(A.x, acc.x, v[j].x);
        acc.y = fmaf(A.y, acc.y, v[j].y);
        acc.z = fmaf(A.z, acc.z, v[j].z);
        acc.w = fmaf(A.w, acc.w, v[j].w);
        if (store)   // evict-first store: don't let out[] evict x[] halo lines from L2
            __stcs(reinterpret_cast<float4*>(po + (size_t)(row + j) * H_DIM), acc);
    }
}

// 4 blocks/SM -> 128-reg budget: enough for two 8xfloat4 buffers (explicit
// double-buffer pipeline) while letting all 512 blocks be resident in one wave.
__global__ __launch_bounds__(TPB, 4)
void LI_scan_kernel(const float* __restrict__ x,
                    const float* __restrict__ tau,
                    float* __restrict__ out) {
    const int chunk       = blockIdx.x;
    const int chunk_start = chunk * CHUNK;
    const int ch          = (blockIdx.y * TPB + threadIdx.x) * 4;

    // Per-channel decay A = exp(tau)
    float4 t = ld4(tau + ch);
    float4 A;
    A.x = expf(t.x); A.y = expf(t.y); A.z = expf(t.z); A.w = expf(t.w);

    // Runtime halo length K: smallest K with Amax^K < 1e-6 (output is O(1),
    // test tolerance is 1e-3 -> 3 orders of margin). Rounded up to a BATCH
    // multiple so every batch is full. Falls back to exact full prefix if A~1.
    float amax = fmaxf(fmaxf(A.x, A.y), fmaxf(A.z, A.w));
    int K;
    if (!(amax < 0.999999f)) {
        K = chunk_start;                       // no usable decay: exact prefix
    } else if (amax <= 1e-12f) {
        K = 0;
    } else {
        float kf = logf(1e-6f) / logf(amax);   // both logs negative -> positive
        int   ki = (int)ceilf(kf);
        if (ki < 0) ki = 0;
        ki = (ki + BATCH - 1) & ~(BATCH - 1);  // round up to multiple of BATCH
        K = ki < chunk_start ? ki : chunk_start;  // chunk_start % BATCH == 0
    }

    // Block-uniform K (keeps batch loop structure aligned across the block)
    __shared__ int sK;
    if (threadIdx.x == 0) sK = 0;
    __syncthreads();
    atomicMax(&sK, K);
    __syncthreads();
    K = sK;

    const float* px = x + ch;
    float*       po = out + ch;

    float4 acc = make_float4(0.f, 0.f, 0.f, 0.f);

    // ---- Fused halo + main loop, software-pipelined (double buffer) ----
    // Rows [chunk_start-K, chunk_start) warm up acc (no stores);
    // rows [chunk_start, chunk_start+CHUNK) also store. K and CHUNK are both
    // multiples of BATCH, so each batch is uniformly halo or main.
    int row = chunk_start - K;
    const int nb = (K + CHUNK) / BATCH;        // >= CHUNK/BATCH = 8

    float4 v0[BATCH], v1[BATCH];
    loadB(v0, px, row);
    int b = 0;
    while (true) {
        if (b + 1 < nb) loadB(v1, px, row + BATCH);      // prefetch next batch
        procB(v0, A, acc, po, row, row >= chunk_start);
        row += BATCH; if (++b >= nb) break;
        if (b + 1 < nb) loadB(v0, px, row + BATCH);      // prefetch next batch
        procB(v1, A, acc, po, row, row >= chunk_start);
        row += BATCH; if (++b >= nb) break;
    }
}

extern "C" void kernel_launch(void* const* d_in, const int* in_sizes, int n_in,
                              void* d_out, int out_size) {
    const float* x   = (const float*)d_in[0];   // (L, H) fp32
    const float* tau = (const float*)d_in[1];   // (H,)   fp32
    float*       out = (float*)d_out;           // (L, H) fp32

    dim3 grid(L_DIM / CHUNK, GROUPS);
    LI_scan_kernel<<<grid, TPB>>>(x, tau, out);
}

// round 4
// speedup vs baseline: 2.4619x; 1.0747x over previous
#include <cuda_runtime.h>
#include <math.h>

// Problem constants (fixed by the dataset)
#define L_DIM 16384
#define H_DIM 1024

// Tiling: each block handles CHUNK rows x 256 channels.
// 128 threads/block, each thread owns 2 adjacent channels (float2).
// float2 (vs float4) halves register-buffer pressure -> 8 blocks/SM resident
// (4096 warps total, ~28/SM) while keeping halo amplification at 2.0x.
#define CHUNK  64
#define GROUPS 4          // H / 256
#define TPB    128
#define BATCH  8          // outstanding LDG.64 per thread per buffer

__device__ __forceinline__ float2 ld2(const float* p) {
    return *reinterpret_cast<const float2*>(p);
}

__device__ __forceinline__ void loadB(float2 v[BATCH], const float* px, int off) {
#pragma unroll
    for (int j = 0; j < BATCH; ++j)
        v[j] = ld2(px + off + j * H_DIM);   // BATCH back-to-back LDG.64
}

__device__ __forceinline__ void procB(const float2 v[BATCH], float2 A, float2& acc,
                                      float* po, int off, bool store) {
#pragma unroll
    for (int j = 0; j < BATCH; ++j) {
        acc.x = fmaf(A.x, acc.x, v[j].x);
        acc.y = fmaf(A.y, acc.y, v[j].y);
        if (store)   // evict-first store: don't let out[] evict x[] halo lines from L2
            __stcs(reinterpret_cast<float2*>(po + off + j * H_DIM), acc);
    }
}

// 8 blocks/SM (1024 threads) -> 64-reg/thread budget. Buffers are 32 regs.
__global__ __launch_bounds__(TPB, 8)
void LI_scan_kernel(const float* __restrict__ x,
                    const float* __restrict__ tau,
                    float* __restrict__ out) {
    const int chunk_start = blockIdx.x * CHUNK;
    const int ch          = (blockIdx.y * TPB + threadIdx.x) * 2;

    // Per-channel decay A = exp(tau)
    float2 t = ld2(tau + ch);
    float2 A;
    A.x = expf(t.x); A.y = expf(t.y);

    // Runtime halo length K: smallest K with Amax^K < 1e-6 (output is O(1),
    // test tolerance is 1e-3 -> 3 orders of margin). Rounded up to a BATCH
    // multiple so every batch is full. Falls back to exact full prefix if A~1.
    float amax = fmaxf(A.x, A.y);
    int K;
    if (!(amax < 0.999999f)) {
        K = chunk_start;                       // no usable decay: exact prefix
    } else if (amax <= 1e-12f) {
        K = 0;
    } else {
        float kf = logf(1e-6f) / logf(amax);   // both logs negative -> positive
        int   ki = (int)ceilf(kf);
        if (ki < 0) ki = 0;
        ki = (ki + BATCH - 1) & ~(BATCH - 1);  // round up to multiple of BATCH
        K = ki < chunk_start ? ki : chunk_start;  // chunk_start % BATCH == 0
    }

    // Block-uniform K (keeps batch loop structure aligned across the block)
    __shared__ int sK;
    if (threadIdx.x == 0) sK = 0;
    __syncthreads();
    atomicMax(&sK, K);
    __syncthreads();
    K = sK;

    const float* px = x + ch;
    float*       po = out + ch;

    float2 acc = make_float2(0.f, 0.f);

    // ---- Fused halo + main loop, software-pipelined (double buffer) ----
    // Rows [chunk_start-K, chunk_start) warm up acc (no stores);
    // rows [chunk_start, chunk_start+CHUNK) also store. K and CHUNK are both
    // multiples of BATCH, so each batch is uniformly halo or main.
    // 32-bit element offsets: L*H = 2^24 fits comfortably.
    int off       = (chunk_start - K) * H_DIM;  // current batch offset
    const int off0 = chunk_start * H_DIM;       // first storing offset
    const int nb  = (K + CHUNK) / BATCH;        // >= CHUNK/BATCH = 8

    float2 v0[BATCH], v1[BATCH];
    loadB(v0, px, off);
    int b = 0;
    while (true) {
        if (b + 1 < nb) loadB(v1, px, off + BATCH * H_DIM);  // prefetch next batch
        procB(v0, A, acc, po, off, off >= off0);
        off += BATCH * H_DIM; if (++b >= nb) break;
        if (b + 1 < nb) loadB(v0, px, off + BATCH * H_DIM);  // prefetch next batch
        procB(v1, A, acc, po, off, off >= off0);
        off += BATCH * H_DIM; if (++b >= nb) break;
    }
}

extern "C" void kernel_launch(void* const* d_in, const int* in_sizes, int n_in,
                              void* d_out, int out_size) {
    const float* x   = (const float*)d_in[0];   // (L, H) fp32
    const float* tau = (const float*)d_in[1];   // (H,)   fp32
    float*       out = (float*)d_out;           // (L, H) fp32

    dim3 grid(L_DIM / CHUNK, GROUPS);
    LI_scan_kernel<<<grid, TPB>>>(x, tau, out);
}